// round 5
// baseline (speedup 1.0000x reference)
#include <cuda_runtime.h>
#include <cstdint>

// Problem constants
#define BB 128
#define TT 512
#define DD 512
#define HH 512
#define G4 2048            // 4*H
#define MX (BB*TT)

// Persistent-kernel tiling
#define NCTA 128
#define ROWS 32            // batch rows per CTA (one quarter)
#define NC   64            // permuted cols per CTA (=> 16 h cols)
#define AST  516           // As word stride (516 % 32 == 4 -> conflict-free frags)
#define BST  516           // Bt word stride
#define ZST  68            // zs word stride

// Device scratch (allocation-free requirement: __device__ globals)
__device__ float g_pre[(size_t)MX * G4];     // x@Wx + b, permuted cols, row m = b*T + t
__device__ float g_Wxp[DD * G4];
__device__ float g_Whp[HH * G4];
__device__ float g_bp[G4];
__device__ float g_h[2][BB * HH];            // ping-pong hidden state (sorted batch order)
__device__ int   g_srcb[BB];                 // sorted pos -> original batch row
__device__ int   g_nws[BB];                  // num_words in sorted (descending) order
__device__ unsigned g_qcnt[4];               // per-quarter barrier counters

__device__ __forceinline__ uint32_t f2tf32(float f) {
    uint32_t u;
    asm("cvt.rna.tf32.f32 %0, %1;" : "=r"(u) : "f"(f));
    return u;
}

__device__ __forceinline__ void mma8(float d[4], const uint32_t a[4], const uint32_t b[2]) {
    asm volatile(
        "mma.sync.aligned.m16n8k8.row.col.f32.tf32.tf32.f32 "
        "{%0,%1,%2,%3}, {%4,%5,%6,%7}, {%8,%9}, {%0,%1,%2,%3};"
        : "+f"(d[0]), "+f"(d[1]), "+f"(d[2]), "+f"(d[3])
        : "r"(a[0]), "r"(a[1]), "r"(a[2]), "r"(a[3]), "r"(b[0]), "r"(b[1]));
}

// ---------------------------------------------------------------------------
// Kernel 0: permute W (gate-blocked cols -> interleaved col' = 4*h + g)
// ---------------------------------------------------------------------------
__global__ void permute_W_kernel(const float* __restrict__ W, const float* __restrict__ bias) {
    int idx = blockIdx.x * 256 + threadIdx.x;
    if (idx < 1024 * 2048) {
        int d = idx >> 11;
        int col = idx & 2047;
        int g = col >> 9;
        int h = col & 511;
        int colp = 4 * h + g;
        float v = W[idx];
        if (d < 512) g_Wxp[d * 2048 + colp] = v;
        else         g_Whp[(d - 512) * 2048 + colp] = v;
    }
    if (idx < 2048) {
        int g = idx >> 9;
        int h = idx & 511;
        g_bp[4 * h + g] = bias[idx];
    }
}

// ---------------------------------------------------------------------------
// Kernel 1: input projection GEMM  g_pre = X @ Wxp + b   (X viewed [65536 x 512])
// ---------------------------------------------------------------------------
__global__ void __launch_bounds__(256) gemm_x_kernel(const float* __restrict__ X) {
    __shared__ uint32_t As[128][33];
    __shared__ uint32_t Bs[32][65];
    const int n0 = blockIdx.x * 64;
    const int m0 = blockIdx.y * 128;
    const int tid = threadIdx.x;
    const int lane = tid & 31;
    const int warp = tid >> 5;
    const int wm = warp >> 1, wn = warp & 1;

    float acc[2][4][4];
    #pragma unroll
    for (int s = 0; s < 2; s++)
        #pragma unroll
        for (int u = 0; u < 4; u++)
            #pragma unroll
            for (int i = 0; i < 4; i++) acc[s][u][i] = 0.f;

    for (int k0 = 0; k0 < 512; k0 += 32) {
        {
            int r = tid >> 1;
            int c = (tid & 1) * 16;
            const float* srcA = X + (size_t)(m0 + r) * 512 + k0 + c;
            #pragma unroll
            for (int i = 0; i < 4; i++) {
                float4 v = *(const float4*)(srcA + 4 * i);
                As[r][c + 4*i + 0] = f2tf32(v.x);
                As[r][c + 4*i + 1] = f2tf32(v.y);
                As[r][c + 4*i + 2] = f2tf32(v.z);
                As[r][c + 4*i + 3] = f2tf32(v.w);
            }
        }
        {
            int r = tid >> 3;
            int c = (tid & 7) * 8;
            const float* srcB = g_Wxp + (size_t)(k0 + r) * 2048 + n0 + c;
            #pragma unroll
            for (int i = 0; i < 2; i++) {
                float4 v = *(const float4*)(srcB + 4 * i);
                Bs[r][c + 4*i + 0] = f2tf32(v.x);
                Bs[r][c + 4*i + 1] = f2tf32(v.y);
                Bs[r][c + 4*i + 2] = f2tf32(v.z);
                Bs[r][c + 4*i + 3] = f2tf32(v.w);
            }
        }
        __syncthreads();

        #pragma unroll
        for (int ks = 0; ks < 4; ks++) {
            uint32_t a[2][4], bb[4][2];
            const int kk = ks * 8 + (lane & 3);
            #pragma unroll
            for (int s = 0; s < 2; s++) {
                int rr = wm * 32 + s * 16 + (lane >> 2);
                a[s][0] = As[rr][kk];
                a[s][1] = As[rr + 8][kk];
                a[s][2] = As[rr][kk + 4];
                a[s][3] = As[rr + 8][kk + 4];
            }
            #pragma unroll
            for (int u = 0; u < 4; u++) {
                int cc = wn * 32 + u * 8 + (lane >> 2);
                bb[u][0] = Bs[kk][cc];
                bb[u][1] = Bs[kk + 4][cc];
            }
            #pragma unroll
            for (int s = 0; s < 2; s++)
                #pragma unroll
                for (int u = 0; u < 4; u++)
                    mma8(acc[s][u], a[s], bb[u]);
        }
        __syncthreads();
    }

    #pragma unroll
    for (int s = 0; s < 2; s++) {
        int row = m0 + wm * 32 + s * 16 + (lane >> 2);
        #pragma unroll
        for (int u = 0; u < 4; u++) {
            int col = n0 + wn * 32 + u * 8 + 2 * (lane & 3);
            size_t base = (size_t)row * 2048 + col;
            g_pre[base]                      = acc[s][u][0] + g_bp[col];
            g_pre[base + 1]                  = acc[s][u][1] + g_bp[col + 1];
            g_pre[base + (size_t)8*2048]     = acc[s][u][2] + g_bp[col];
            g_pre[base + (size_t)8*2048 + 1] = acc[s][u][3] + g_bp[col + 1];
        }
    }
}

// ---------------------------------------------------------------------------
// Kernel 2a: sort batch rows by num_words descending (stable).
// ---------------------------------------------------------------------------
__global__ void sort_kernel(const int* __restrict__ nw) {
    int b = threadIdx.x;
    if (b < BB) {
        int my = nw[b];
        int rank = 0;
        for (int j = 0; j < BB; j++) {
            int v = nw[j];
            rank += (v > my) || (v == my && j < b);
        }
        g_srcb[rank] = b;
        g_nws[rank] = my;
    }
}

// ---------------------------------------------------------------------------
// Kernel 2b: init — reset per-quarter barrier counters, publish tf32-rounded
// initial h in sorted batch order.
// ---------------------------------------------------------------------------
__global__ void init_state_kernel(const float* __restrict__ ih) {
    int i = blockIdx.x * 256 + threadIdx.x;
    if (i < 4) g_qcnt[i] = 0u;
    if (i < BB * HH) {
        int srow = i >> 9;
        int col = i & 511;
        int borig = g_srcb[srow];
        g_h[0][i] = __uint_as_float(f2tf32(ih[borig * HH + col]));
    }
}

// ---------------------------------------------------------------------------
// Kernel 3: persistent LSTM recurrence.
// 128 CTAs = 4 batch quarters (sorted, independent) x 32 col' chunks.
// Cross-CTA sync is QUARTER-LOCAL: 32-CTA release/acquire barrier (CG-style,
// no full threadfence / L1 flush). Quarters run fully decoupled; a finished
// quarter leaves the protocol, bulk-writes its zeros, and exits.
// ---------------------------------------------------------------------------
__global__ void __launch_bounds__(256, 1) lstm_persist_kernel(
    const float* __restrict__ ic, const float* __restrict__ ih,
    float* __restrict__ out, float* __restrict__ c_final, float* __restrict__ h_final)
{
    extern __shared__ unsigned char smraw[];
    uint32_t* As = (uint32_t*)smraw;                       // [32][AST] words
    float*    zs = (float*)smraw;                          // [4][32][ZST] overlay on As
    uint32_t* Bt = (uint32_t*)(smraw + ROWS * AST * 4);    // [64][BST] words (B^T)

    const int tid  = threadIdx.x;
    const int lane = tid & 31;
    const int warp = tid >> 5;
    const int rb = blockIdx.x & 3;        // batch quarter (sorted order)
    const int cn = blockIdx.x >> 2;       // 0..31 col' chunk
    const int n0 = cn * NC;               // col' base

    // --- load Wh slice into SMEM transposed: Bt[cc][k], tf32 ---
    #pragma unroll 4
    for (int j = 0; j < (NC * 512) / 256; j++) {
        int idx = tid + 256 * j;
        int cc = idx & (NC - 1);
        int k  = idx >> 6;
        Bt[cc * BST + k] = f2tf32(g_Whp[(size_t)k * 2048 + n0 + cc]);
    }

    // --- epilogue mapping: thread owns (srow, hc0) and (srow, hc0+1) ---
    const int r_ep = tid & 31;                 // local batch row (== lane)
    const int hl2  = (tid >> 5) * 2;           // local h col pair (0,2,..,14)
    const int srow = rb * ROWS + r_ep;         // sorted batch row
    const int borig = g_srcb[srow];            // original batch row
    const int mynw  = g_nws[srow];
    const int qmax  = g_nws[rb * ROWS];        // max num_words in this quarter
    float c0  = ic[borig * HH + cn * 16 + hl2];
    float c1  = ic[borig * HH + cn * 16 + hl2 + 1];
    float hr0 = ih[borig * HH + cn * 16 + hl2];
    float hr1 = ih[borig * HH + cn * 16 + hl2 + 1];
    const size_t outcol = (size_t)borig * HH + cn * 16 + hl2;

    // --- MMA mapping: 8 warps = 2 n-halves x 4 K-slices; warp tile 32x32 ---
    const int wn = warp & 1;
    const int kw = warp >> 1;
    const int kbase = kw * 128;
    const int ln4 = lane >> 2;
    const int kl  = lane & 3;

    // --- A-fill mapping ---
    const int fr = tid >> 3;                   // row 0..31
    const int fc = tid & 7;                    // float4 group

    unsigned* const qcnt = &g_qcnt[rb];

    __syncthreads();                           // Bt ready

    // prefetch pre-activations for step 0
    float4 p0, p1;
    if (qmax > 0) {
        size_t pbase = ((size_t)borig * TT) * 2048 + n0 + hl2 * 4;
        p0 = __ldcs((const float4*)(g_pre + pbase));
        p1 = __ldcs((const float4*)(g_pre + pbase + 4));
    }

    for (int t = 0; t < qmax; t++) {
        const float* __restrict__ h_in  = g_h[t & 1];
        float*       __restrict__ h_out = g_h[(t & 1) ^ 1];

        // fill As with this quarter's 32 h rows (L2-coherent, raw copy)
        {
            const float4* src = (const float4*)(h_in + (size_t)(rb * ROWS + fr) * HH) + fc;
            #pragma unroll
            for (int j = 0; j < 16; j++) {
                float4 v = __ldcg(src + 8 * j);
                *(float4*)&As[fr * AST + (fc + 8 * j) * 4] = v;
            }
        }
        __syncthreads();

        // GEMM: [32 x 128] @ [128 x 32] per warp (K slice kw, n half wn)
        float acc[2][4][4];
        #pragma unroll
        for (int s = 0; s < 2; s++)
            #pragma unroll
            for (int u = 0; u < 4; u++)
                #pragma unroll
                for (int i = 0; i < 4; i++) acc[s][u][i] = 0.f;

        #pragma unroll 8
        for (int ks = 0; ks < 16; ks++) {
            const int kk = kbase + ks * 8 + kl;
            uint32_t a[2][4], bb[4][2];
            #pragma unroll
            for (int s = 0; s < 2; s++) {
                int rr = s * 16 + ln4;
                a[s][0] = As[rr * AST + kk];
                a[s][1] = As[(rr + 8) * AST + kk];
                a[s][2] = As[rr * AST + kk + 4];
                a[s][3] = As[(rr + 8) * AST + kk + 4];
            }
            #pragma unroll
            for (int u = 0; u < 4; u++) {
                int cc = wn * 32 + u * 8 + ln4;
                bb[u][0] = Bt[cc * BST + kk];
                bb[u][1] = Bt[cc * BST + kk + 4];
            }
            #pragma unroll
            for (int s = 0; s < 2; s++)
                #pragma unroll
                for (int u = 0; u < 4; u++)
                    mma8(acc[s][u], a[s], bb[u]);
        }
        __syncthreads();   // all As reads done before zs overlay writes

        // store partials: zs[kw][row][col]
        {
            int zcb = wn * 32 + 2 * kl;
            #pragma unroll
            for (int s = 0; s < 2; s++) {
                int row = s * 16 + ln4;
                #pragma unroll
                for (int u = 0; u < 4; u++) {
                    int col = zcb + u * 8;
                    *(float2*)&zs[(kw * 32 + row) * ZST + col]     =
                        make_float2(acc[s][u][0], acc[s][u][1]);
                    *(float2*)&zs[(kw * 32 + row + 8) * ZST + col] =
                        make_float2(acc[s][u][2], acc[s][u][3]);
                }
            }
        }
        __syncthreads();

        // reduce 4 K-partials + fused gate epilogue (2 owned h cols)
        float4 z0 = make_float4(0.f, 0.f, 0.f, 0.f);
        float4 z1 = make_float4(0.f, 0.f, 0.f, 0.f);
        #pragma unroll
        for (int s = 0; s < 4; s++) {
            const float* zp = zs + ((s * 32 + r_ep) * ZST + hl2 * 4);
            float4 a0 = *(const float4*)zp;
            float4 a1 = *(const float4*)(zp + 4);
            z0.x += a0.x; z0.y += a0.y; z0.z += a0.z; z0.w += a0.w;
            z1.x += a1.x; z1.y += a1.y; z1.z += a1.z; z1.w += a1.w;
        }

        float zi0 = z0.x + p0.x, zj0 = z0.y + p0.y, zf0 = z0.z + p0.z, zo0 = z0.w + p0.w;
        float zi1 = z1.x + p1.x, zj1 = z1.y + p1.y, zf1 = z1.z + p1.z, zo1 = z1.w + p1.w;

        float si0 = 1.f / (1.f + __expf(-zi0));
        float sf0 = 1.f / (1.f + __expf(-(zf0 + 1.0f)));
        float so0 = 1.f / (1.f + __expf(-zo0));
        float tj0 = tanhf(zj0);
        float nc0 = c0 * sf0 + si0 * tj0;
        float nh0 = tanhf(nc0) * so0;

        float si1 = 1.f / (1.f + __expf(-zi1));
        float sf1 = 1.f / (1.f + __expf(-(zf1 + 1.0f)));
        float so1 = 1.f / (1.f + __expf(-zo1));
        float tj1 = tanhf(zj1);
        float nc1 = c1 * sf1 + si1 * tj1;
        float nh1 = tanhf(nc1) * so1;

        bool m = t < mynw;
        c0 = m ? nc0 : c0;   c1 = m ? nc1 : c1;
        hr0 = m ? nh0 : hr0; hr1 = m ? nh1 : hr1;

        size_t sidx = (size_t)srow * HH + cn * 16 + hl2;
        *(float2*)&h_out[sidx] = make_float2(__uint_as_float(f2tf32(hr0)),
                                             __uint_as_float(f2tf32(hr1)));
        *(float2*)&out[(size_t)t * (BB * HH) + outcol] =
            make_float2(m ? nh0 : 0.f, m ? nh1 : 0.f);

        // quarter-local barrier — only while a next step will consume h
        if (t + 1 < qmax) {
            // prefetch next step's pre-activations; latency overlaps the spin
            size_t pbase = ((size_t)borig * TT + (t + 1)) * 2048 + n0 + hl2 * 4;
            p0 = __ldcs((const float4*)(g_pre + pbase));
            p1 = __ldcs((const float4*)(g_pre + pbase + 4));

            __syncthreads();                       // all h_out stores issued CTA-wide
            if (tid == 0) {
                asm volatile("red.release.gpu.add.u32 [%0], %1;"
                             :: "l"(qcnt), "r"(1u) : "memory");
                unsigned target = 32u * (unsigned)(t + 1);
                unsigned v;
                do {
                    asm volatile("ld.acquire.gpu.u32 %0, [%1];"
                                 : "=r"(v) : "l"(qcnt) : "memory");
                } while (v < target);
            }
            __syncthreads();                       // acquire propagates CTA-wide
        }
    }

    // bulk zeros for the inactive tail (no synchronization needed)
    for (int t = qmax; t < TT; t++)
        *(float2*)&out[(size_t)t * (BB * HH) + outcol] = make_float2(0.f, 0.f);

    // final states (each (b,h) pair owned by exactly one thread)
    *(float2*)&c_final[outcol] = make_float2(c0, c1);
    *(float2*)&h_final[outcol] = make_float2(hr0, hr1);
}

// ---------------------------------------------------------------------------
extern "C" void kernel_launch(void* const* d_in, const int* in_sizes, int n_in,
                              void* d_out, int out_size) {
    const float* x    = (const float*)d_in[0];  // [B,T,D]
    const int*   nw   = (const int*)  d_in[1];  // [B]
    const float* ic   = (const float*)d_in[2];  // [B,H]
    const float* ih   = (const float*)d_in[3];  // [B,H]
    const float* W    = (const float*)d_in[4];  // [D+H, 4H]
    const float* bias = (const float*)d_in[5];  // [4H]

    float* out     = (float*)d_out;
    float* c_final = out + (size_t)TT * BB * HH;
    float* h_final = c_final + (size_t)BB * HH;

    const int smem_bytes = ROWS * AST * 4 + NC * BST * 4;   // 198144
    cudaFuncSetAttribute(lstm_persist_kernel,
                         cudaFuncAttributeMaxDynamicSharedMemorySize, smem_bytes);

    permute_W_kernel<<<8192, 256>>>(W, bias);
    gemm_x_kernel<<<dim3(32, 512), 256>>>(x);
    sort_kernel<<<1, 128>>>(nw);
    init_state_kernel<<<(BB * HH + 255) / 256, 256>>>(ih);
    lstm_persist_kernel<<<NCTA, 256, smem_bytes>>>(ic, ih, out, c_final, h_final);
}

// round 6
// speedup vs baseline: 1.4592x; 1.4592x over previous
#include <cuda_runtime.h>
#include <cuda_fp16.h>
#include <cstdint>

// Problem constants
#define BB 128
#define TT 512
#define DD 512
#define HH 512
#define G4 2048            // 4*H
#define MX (BB*TT)

// Persistent-kernel tiling
#define NCTA 128
#define ROWS 32            // batch rows per CTA (one quarter)
#define NC   64            // permuted cols per CTA (=> 16 h cols)
#define AS2  260           // As stride in b32 units (256 + 4; 260%32==4 -> conflict-free)
#define BS2  260           // Bt stride in b32 units
#define ZST  68            // zs stride in floats

// Device scratch (allocation-free requirement: __device__ globals)
__device__ __half g_preh[(size_t)MX * G4];   // 256 MB: x@Wx + b (fp16), permuted cols
__device__ float  g_Wxp[DD * G4];            // permuted input weights (fp32, tf32 path)
__device__ __half g_WhT[G4 * HH];            // permuted recurrent weights, TRANSPOSED [col'][k]
__device__ float  g_bp[G4];                  // permuted bias
__device__ __half g_hh[2][BB * HH];          // ping-pong hidden state (fp16, sorted order)
__device__ int    g_srcb[BB];                // sorted pos -> original batch row
__device__ int    g_nws[BB];                 // num_words, sorted descending
__device__ unsigned g_qcnt[4];               // per-quarter barrier counters

__device__ __forceinline__ uint32_t f2tf32(float f) {
    uint32_t u;
    asm("cvt.rna.tf32.f32 %0, %1;" : "=r"(u) : "f"(f));
    return u;
}

__device__ __forceinline__ void mma8(float d[4], const uint32_t a[4], const uint32_t b[2]) {
    asm volatile(
        "mma.sync.aligned.m16n8k8.row.col.f32.tf32.tf32.f32 "
        "{%0,%1,%2,%3}, {%4,%5,%6,%7}, {%8,%9}, {%0,%1,%2,%3};"
        : "+f"(d[0]), "+f"(d[1]), "+f"(d[2]), "+f"(d[3])
        : "r"(a[0]), "r"(a[1]), "r"(a[2]), "r"(a[3]), "r"(b[0]), "r"(b[1]));
}

__device__ __forceinline__ void mma16h(float d[4], const uint32_t a[4], const uint32_t b[2]) {
    asm volatile(
        "mma.sync.aligned.m16n8k16.row.col.f32.f16.f16.f32 "
        "{%0,%1,%2,%3}, {%4,%5,%6,%7}, {%8,%9}, {%0,%1,%2,%3};"
        : "+f"(d[0]), "+f"(d[1]), "+f"(d[2]), "+f"(d[3])
        : "r"(a[0]), "r"(a[1]), "r"(a[2]), "r"(a[3]), "r"(b[0]), "r"(b[1]));
}

// ---------------------------------------------------------------------------
// Kernel 0: permute W. col' = 4*h + g. Wx kept fp32 row-major; Wh stored
// fp16 TRANSPOSED: g_WhT[col'][k].
// ---------------------------------------------------------------------------
__global__ void permute_W_kernel(const float* __restrict__ W, const float* __restrict__ bias) {
    int idx = blockIdx.x * 256 + threadIdx.x;
    if (idx < 1024 * 2048) {
        int d = idx >> 11;
        int col = idx & 2047;
        int g = col >> 9;
        int h = col & 511;
        int colp = 4 * h + g;
        float v = W[idx];
        if (d < 512) g_Wxp[d * 2048 + colp] = v;
        else         g_WhT[(size_t)colp * 512 + (d - 512)] = __float2half_rn(v);
    }
    if (idx < 2048) {
        int g = idx >> 9;
        int h = idx & 511;
        g_bp[4 * h + g] = bias[idx];
    }
}

// ---------------------------------------------------------------------------
// Kernel 1: input projection GEMM  g_preh = fp16(X @ Wxp + b), tf32 MMA.
// Early-exits blocks whose 128 timesteps are all masked (t0 >= num_words[b]).
// ---------------------------------------------------------------------------
__global__ void __launch_bounds__(256) gemm_x_kernel(const float* __restrict__ X,
                                                     const int* __restrict__ nw) {
    const int n0 = blockIdx.x * 64;
    const int m0 = blockIdx.y * 128;
    {
        int b = m0 >> 9;
        int t0 = m0 & 511;
        if (t0 >= nw[b]) return;          // whole block masked: g_preh never consumed
    }
    __shared__ uint32_t As[128][33];
    __shared__ uint32_t Bs[32][65];
    const int tid = threadIdx.x;
    const int lane = tid & 31;
    const int warp = tid >> 5;
    const int wm = warp >> 1, wn = warp & 1;

    float acc[2][4][4];
    #pragma unroll
    for (int s = 0; s < 2; s++)
        #pragma unroll
        for (int u = 0; u < 4; u++)
            #pragma unroll
            for (int i = 0; i < 4; i++) acc[s][u][i] = 0.f;

    for (int k0 = 0; k0 < 512; k0 += 32) {
        {
            int r = tid >> 1;
            int c = (tid & 1) * 16;
            const float* srcA = X + (size_t)(m0 + r) * 512 + k0 + c;
            #pragma unroll
            for (int i = 0; i < 4; i++) {
                float4 v = *(const float4*)(srcA + 4 * i);
                As[r][c + 4*i + 0] = f2tf32(v.x);
                As[r][c + 4*i + 1] = f2tf32(v.y);
                As[r][c + 4*i + 2] = f2tf32(v.z);
                As[r][c + 4*i + 3] = f2tf32(v.w);
            }
        }
        {
            int r = tid >> 3;
            int c = (tid & 7) * 8;
            const float* srcB = g_Wxp + (size_t)(k0 + r) * 2048 + n0 + c;
            #pragma unroll
            for (int i = 0; i < 2; i++) {
                float4 v = *(const float4*)(srcB + 4 * i);
                Bs[r][c + 4*i + 0] = f2tf32(v.x);
                Bs[r][c + 4*i + 1] = f2tf32(v.y);
                Bs[r][c + 4*i + 2] = f2tf32(v.z);
                Bs[r][c + 4*i + 3] = f2tf32(v.w);
            }
        }
        __syncthreads();

        #pragma unroll
        for (int ks = 0; ks < 4; ks++) {
            uint32_t a[2][4], bb[4][2];
            const int kk = ks * 8 + (lane & 3);
            #pragma unroll
            for (int s = 0; s < 2; s++) {
                int rr = wm * 32 + s * 16 + (lane >> 2);
                a[s][0] = As[rr][kk];
                a[s][1] = As[rr + 8][kk];
                a[s][2] = As[rr][kk + 4];
                a[s][3] = As[rr + 8][kk + 4];
            }
            #pragma unroll
            for (int u = 0; u < 4; u++) {
                int cc = wn * 32 + u * 8 + (lane >> 2);
                bb[u][0] = Bs[kk][cc];
                bb[u][1] = Bs[kk + 4][cc];
            }
            #pragma unroll
            for (int s = 0; s < 2; s++)
                #pragma unroll
                for (int u = 0; u < 4; u++)
                    mma8(acc[s][u], a[s], bb[u]);
        }
        __syncthreads();
    }

    #pragma unroll
    for (int s = 0; s < 2; s++) {
        int row = m0 + wm * 32 + s * 16 + (lane >> 2);
        #pragma unroll
        for (int u = 0; u < 4; u++) {
            int col = n0 + wn * 32 + u * 8 + 2 * (lane & 3);
            float b0 = g_bp[col], b1 = g_bp[col + 1];
            size_t base = (size_t)row * 2048 + col;
            *(__half2*)(g_preh + base) =
                __floats2half2_rn(acc[s][u][0] + b0, acc[s][u][1] + b1);
            *(__half2*)(g_preh + base + (size_t)8 * 2048) =
                __floats2half2_rn(acc[s][u][2] + b0, acc[s][u][3] + b1);
        }
    }
}

// ---------------------------------------------------------------------------
// Kernel 2a: sort batch rows by num_words descending (stable).
// ---------------------------------------------------------------------------
__global__ void sort_kernel(const int* __restrict__ nw) {
    int b = threadIdx.x;
    if (b < BB) {
        int my = nw[b];
        int rank = 0;
        for (int j = 0; j < BB; j++) {
            int v = nw[j];
            rank += (v > my) || (v == my && j < b);
        }
        g_srcb[rank] = b;
        g_nws[rank] = my;
    }
}

// ---------------------------------------------------------------------------
// Kernel 2b: init — reset counters, publish fp16 initial h (sorted order).
// ---------------------------------------------------------------------------
__global__ void init_state_kernel(const float* __restrict__ ih) {
    int i = blockIdx.x * 256 + threadIdx.x;
    if (i < 4) g_qcnt[i] = 0u;
    if (i < BB * HH) {
        int srow = i >> 9;
        int col = i & 511;
        int borig = g_srcb[srow];
        g_hh[0][i] = __float2half_rn(ih[borig * HH + col]);
    }
}

// ---------------------------------------------------------------------------
// Kernel 3: persistent LSTM recurrence, fp16 HMMA (m16n8k16, fp32 accum).
// 128 CTAs = 4 sorted batch quarters x 32 col' chunks of 64.
// Quarter-local 32-CTA release/acquire barrier. Finished quarters exit early.
// ---------------------------------------------------------------------------
__global__ void __launch_bounds__(256, 1) lstm_persist_kernel(
    const float* __restrict__ ic, const float* __restrict__ ih,
    float* __restrict__ out, float* __restrict__ c_final, float* __restrict__ h_final)
{
    extern __shared__ unsigned char smraw[];
    uint32_t* As32 = (uint32_t*)smraw;                                   // [32][AS2] b32 (fp16x2)
    uint32_t* Bt32 = (uint32_t*)(smraw + ROWS * AS2 * 4);                // [64][BS2] b32 (B^T)
    float*    zs   = (float*)(smraw + ROWS * AS2 * 4 + NC * BS2 * 4);    // [4][32][ZST]

    const int tid  = threadIdx.x;
    const int lane = tid & 31;
    const int warp = tid >> 5;
    const int rb = blockIdx.x & 3;        // batch quarter (sorted order)
    const int cn = blockIdx.x >> 2;       // 0..31 col' chunk
    const int n0 = cn * NC;               // col' base

    // --- one-time: load Wh^T slice into SMEM (fp16 pairs along k) ---
    {
        int cc  = tid >> 2;               // 0..63
        int seg = tid & 3;                // quarter of the 512-k row
        const uint4* src = (const uint4*)(g_WhT + (size_t)(n0 + cc) * 512 + seg * 128);
        uint32_t* dst = Bt32 + cc * BS2 + seg * 64;
        #pragma unroll
        for (int i = 0; i < 16; i++) {
            uint4 v = src[i];
            *(uint4*)(dst + i * 4) = v;
        }
    }

    // --- epilogue mapping: thread owns (srow, hc0) and (srow, hc0+1) ---
    const int r_ep = tid & 31;                 // local batch row
    const int hl2  = (tid >> 5) * 2;           // local h col pair (0,2,..,14)
    const int srow = rb * ROWS + r_ep;         // sorted batch row
    const int borig = g_srcb[srow];            // original batch row
    const int mynw  = g_nws[srow];
    const int qmax  = g_nws[rb * ROWS];        // max num_words in this quarter
    float c0  = ic[borig * HH + cn * 16 + hl2];
    float c1  = ic[borig * HH + cn * 16 + hl2 + 1];
    float hr0 = ih[borig * HH + cn * 16 + hl2];
    float hr1 = ih[borig * HH + cn * 16 + hl2 + 1];
    const size_t outcol = (size_t)borig * HH + cn * 16 + hl2;

    // --- MMA mapping: 8 warps = 2 n-halves x 4 K-slices; warp tile 32x32 ---
    const int wn = warp & 1;
    const int kw = warp >> 1;
    const int kwb = kw * 64;                   // K-slice base in b32 units
    const int ln4 = lane >> 2;
    const int kl  = lane & 3;

    // --- A-fill mapping: 32 rows x 64 uint4 (8 halves each) ---
    const int fr = tid >> 3;                   // row 0..31
    const int fc = tid & 7;                    // uint4 group

    unsigned* const qcnt = &g_qcnt[rb];

    __syncthreads();                           // Bt ready

    // prefetch pre-activations for step 0 (8 fp16 gate values)
    uint4 praw = make_uint4(0, 0, 0, 0);
    if (qmax > 0)
        praw = __ldcs((const uint4*)(g_preh + ((size_t)borig * TT) * 2048 + n0 + hl2 * 4));

    for (int t = 0; t < qmax; t++) {
        const __half* __restrict__ h_in  = g_hh[t & 1];
        __half*       __restrict__ h_out = g_hh[(t & 1) ^ 1];

        // fill As with this quarter's 32 h rows (fp16, raw copy)
        {
            const uint4* src = (const uint4*)(h_in + (size_t)(rb * ROWS + fr) * HH) + fc;
            uint32_t* dst = As32 + fr * AS2;
            #pragma unroll
            for (int j = 0; j < 8; j++) {
                uint4 v = __ldcg(src + 8 * j);
                *(uint4*)(dst + (fc + 8 * j) * 4) = v;
            }
        }
        __syncthreads();

        // GEMM: [32 x 128] @ [128 x 32] per warp (K-slice kw, n-half wn)
        float acc[2][4][4];
        #pragma unroll
        for (int s = 0; s < 2; s++)
            #pragma unroll
            for (int u = 0; u < 4; u++)
                #pragma unroll
                for (int i = 0; i < 4; i++) acc[s][u][i] = 0.f;

        #pragma unroll
        for (int ks = 0; ks < 8; ks++) {
            const int kb = kwb + ks * 8 + kl;
            uint32_t a[2][4], bb[4][2];
            #pragma unroll
            for (int s = 0; s < 2; s++) {
                int rr = s * 16 + ln4;
                a[s][0] = As32[rr * AS2 + kb];
                a[s][1] = As32[(rr + 8) * AS2 + kb];
                a[s][2] = As32[rr * AS2 + kb + 4];
                a[s][3] = As32[(rr + 8) * AS2 + kb + 4];
            }
            #pragma unroll
            for (int u = 0; u < 4; u++) {
                int cc = wn * 32 + u * 8 + ln4;
                bb[u][0] = Bt32[cc * BS2 + kb];
                bb[u][1] = Bt32[cc * BS2 + kb + 4];
            }
            #pragma unroll
            for (int s = 0; s < 2; s++)
                #pragma unroll
                for (int u = 0; u < 4; u++)
                    mma16h(acc[s][u], a[s], bb[u]);
        }

        // store partials: zs[kw][row][col] (separate region — no sync needed)
        {
            int zcb = wn * 32 + 2 * kl;
            #pragma unroll
            for (int s = 0; s < 2; s++) {
                int row = s * 16 + ln4;
                #pragma unroll
                for (int u = 0; u < 4; u++) {
                    int col = zcb + u * 8;
                    *(float2*)&zs[(kw * 32 + row) * ZST + col]     =
                        make_float2(acc[s][u][0], acc[s][u][1]);
                    *(float2*)&zs[(kw * 32 + row + 8) * ZST + col] =
                        make_float2(acc[s][u][2], acc[s][u][3]);
                }
            }
        }
        __syncthreads();

        // reduce 4 K-partials + fused gate epilogue (2 owned h cols)
        float4 z0 = make_float4(0.f, 0.f, 0.f, 0.f);
        float4 z1 = make_float4(0.f, 0.f, 0.f, 0.f);
        #pragma unroll
        for (int s = 0; s < 4; s++) {
            const float* zp = zs + ((s * 32 + r_ep) * ZST + hl2 * 4);
            float4 a0 = *(const float4*)zp;
            float4 a1 = *(const float4*)(zp + 4);
            z0.x += a0.x; z0.y += a0.y; z0.z += a0.z; z0.w += a0.w;
            z1.x += a1.x; z1.y += a1.y; z1.z += a1.z; z1.w += a1.w;
        }

        // unpack prefetched fp16 pre-activations
        const __half2* ph = (const __half2*)&praw;
        float2 q0 = __half22float2(ph[0]);   // (i,j) of hc0
        float2 q1 = __half22float2(ph[1]);   // (f,o) of hc0
        float2 q2 = __half22float2(ph[2]);   // (i,j) of hc0+1
        float2 q3 = __half22float2(ph[3]);   // (f,o) of hc0+1

        float zi0 = z0.x + q0.x, zj0 = z0.y + q0.y, zf0 = z0.z + q1.x, zo0 = z0.w + q1.y;
        float zi1 = z1.x + q2.x, zj1 = z1.y + q2.y, zf1 = z1.z + q3.x, zo1 = z1.w + q3.y;

        float si0 = 1.f / (1.f + __expf(-zi0));
        float sf0 = 1.f / (1.f + __expf(-(zf0 + 1.0f)));
        float so0 = 1.f / (1.f + __expf(-zo0));
        float tj0 = tanhf(zj0);
        float nc0 = c0 * sf0 + si0 * tj0;
        float nh0 = tanhf(nc0) * so0;

        float si1 = 1.f / (1.f + __expf(-zi1));
        float sf1 = 1.f / (1.f + __expf(-(zf1 + 1.0f)));
        float so1 = 1.f / (1.f + __expf(-zo1));
        float tj1 = tanhf(zj1);
        float nc1 = c1 * sf1 + si1 * tj1;
        float nh1 = tanhf(nc1) * so1;

        bool m = t < mynw;
        c0 = m ? nc0 : c0;   c1 = m ? nc1 : c1;
        hr0 = m ? nh0 : hr0; hr1 = m ? nh1 : hr1;

        size_t sidx = (size_t)srow * HH + cn * 16 + hl2;
        *(__half2*)(h_out + sidx) = __floats2half2_rn(hr0, hr1);
        *(float2*)&out[(size_t)t * (BB * HH) + outcol] =
            make_float2(m ? nh0 : 0.f, m ? nh1 : 0.f);

        // quarter-local barrier — only while a next step will consume h
        if (t + 1 < qmax) {
            praw = __ldcs((const uint4*)(g_preh +
                       ((size_t)borig * TT + (t + 1)) * 2048 + n0 + hl2 * 4));

            __syncthreads();                       // all h_out stores issued CTA-wide
            if (tid == 0) {
                asm volatile("red.release.gpu.add.u32 [%0], %1;"
                             :: "l"(qcnt), "r"(1u) : "memory");
                unsigned target = 32u * (unsigned)(t + 1);
                unsigned v;
                do {
                    asm volatile("ld.acquire.gpu.u32 %0, [%1];"
                                 : "=r"(v) : "l"(qcnt) : "memory");
                } while (v < target);
            }
            __syncthreads();                       // acquire propagates CTA-wide
        }
    }

    // bulk zeros for the inactive tail (off the critical path)
    for (int t = qmax; t < TT; t++)
        *(float2*)&out[(size_t)t * (BB * HH) + outcol] = make_float2(0.f, 0.f);

    // final states (each (b,h) pair owned by exactly one thread)
    *(float2*)&c_final[outcol] = make_float2(c0, c1);
    *(float2*)&h_final[outcol] = make_float2(hr0, hr1);
}

// ---------------------------------------------------------------------------
extern "C" void kernel_launch(void* const* d_in, const int* in_sizes, int n_in,
                              void* d_out, int out_size) {
    const float* x    = (const float*)d_in[0];  // [B,T,D]
    const int*   nw   = (const int*)  d_in[1];  // [B]
    const float* ic   = (const float*)d_in[2];  // [B,H]
    const float* ih   = (const float*)d_in[3];  // [B,H]
    const float* W    = (const float*)d_in[4];  // [D+H, 4H]
    const float* bias = (const float*)d_in[5];  // [4H]

    float* out     = (float*)d_out;
    float* c_final = out + (size_t)TT * BB * HH;
    float* h_final = c_final + (size_t)BB * HH;

    const int smem_bytes = ROWS * AS2 * 4 + NC * BS2 * 4 + 4 * ROWS * ZST * 4; // 134656
    cudaFuncSetAttribute(lstm_persist_kernel,
                         cudaFuncAttributeMaxDynamicSharedMemorySize, smem_bytes);

    permute_W_kernel<<<8192, 256>>>(W, bias);
    gemm_x_kernel<<<dim3(32, 512), 256>>>(x, nw);
    sort_kernel<<<1, 128>>>(nw);
    init_state_kernel<<<(BB * HH + 255) / 256, 256>>>(ih);
    lstm_persist_kernel<<<NCTA, 256, smem_bytes>>>(ic, ih, out, c_final, h_final);
}

// round 9
// speedup vs baseline: 1.4767x; 1.0120x over previous
#include <cuda_runtime.h>
#include <cuda_fp16.h>
#include <cstdint>

// Problem constants
#define BB 128
#define TT 512
#define DD 512
#define HH 512
#define G4 2048            // 4*H
#define MX (BB*TT)

// Persistent-kernel tiling
#define NCTA 128
#define ROWS 32            // batch rows per CTA (one quarter)
#define NC   64            // permuted cols per CTA (=> 16 h cols)
#define AS2  260           // As stride in b32 units (256 + 4; 260%32==4 -> conflict-free)
#define BS2  260           // Bt stride in b32 units
#define ZST  68            // zs stride in floats

// Device scratch (allocation-free requirement: __device__ globals)
__device__ __half g_preh[(size_t)MX * G4];   // 256 MB: x@Wx + b (fp16), permuted cols
__device__ float  g_Wxp[DD * G4];            // permuted input weights (fp32, tf32 path)
__device__ __half g_WhT[G4 * HH];            // permuted recurrent weights, TRANSPOSED [col'][k]
__device__ float  g_bp[G4];                  // permuted bias
__device__ __half g_hh[2][BB * HH];          // ping-pong hidden state (fp16, sorted order)
__device__ int    g_srcb[BB];                // sorted pos -> original batch row
__device__ int    g_nws[BB];                 // num_words, sorted descending
__device__ unsigned g_qcnt[4];               // per-quarter barrier counters

__device__ __forceinline__ uint32_t f2tf32(float f) {
    uint32_t u;
    asm("cvt.rna.tf32.f32 %0, %1;" : "=r"(u) : "f"(f));
    return u;
}

__device__ __forceinline__ void mma8(float d[4], const uint32_t a[4], const uint32_t b[2]) {
    asm volatile(
        "mma.sync.aligned.m16n8k8.row.col.f32.tf32.tf32.f32 "
        "{%0,%1,%2,%3}, {%4,%5,%6,%7}, {%8,%9}, {%0,%1,%2,%3};"
        : "+f"(d[0]), "+f"(d[1]), "+f"(d[2]), "+f"(d[3])
        : "r"(a[0]), "r"(a[1]), "r"(a[2]), "r"(a[3]), "r"(b[0]), "r"(b[1]));
}

__device__ __forceinline__ void mma16h(float d[4], const uint32_t a[4], const uint32_t b[2]) {
    asm volatile(
        "mma.sync.aligned.m16n8k16.row.col.f32.f16.f16.f32 "
        "{%0,%1,%2,%3}, {%4,%5,%6,%7}, {%8,%9}, {%0,%1,%2,%3};"
        : "+f"(d[0]), "+f"(d[1]), "+f"(d[2]), "+f"(d[3])
        : "r"(a[0]), "r"(a[1]), "r"(a[2]), "r"(a[3]), "r"(b[0]), "r"(b[1]));
}

// ---------------------------------------------------------------------------
// Kernel 0: permute W. col' = 4*h + g. Wx fp32 row-major; Wh fp16 transposed.
// ---------------------------------------------------------------------------
__global__ void permute_W_kernel(const float* __restrict__ W, const float* __restrict__ bias) {
    int idx = blockIdx.x * 256 + threadIdx.x;
    if (idx < 1024 * 2048) {
        int d = idx >> 11;
        int col = idx & 2047;
        int g = col >> 9;
        int h = col & 511;
        int colp = 4 * h + g;
        float v = W[idx];
        if (d < 512) g_Wxp[d * 2048 + colp] = v;
        else         g_WhT[(size_t)colp * 512 + (d - 512)] = __float2half_rn(v);
    }
    if (idx < 2048) {
        int g = idx >> 9;
        int h = idx & 511;
        g_bp[4 * h + g] = bias[idx];
    }
}

// ---------------------------------------------------------------------------
// Kernel 1: input projection GEMM  g_preh = fp16(X @ Wxp + b), tf32 MMA.
// Skips blocks whose 128 timesteps are all masked.
// ---------------------------------------------------------------------------
__global__ void __launch_bounds__(256) gemm_x_kernel(const float* __restrict__ X,
                                                     const int* __restrict__ nw) {
    const int n0 = blockIdx.x * 64;
    const int m0 = blockIdx.y * 128;
    {
        int b = m0 >> 9;
        int t0 = m0 & 511;
        if (t0 >= nw[b]) return;
    }
    __shared__ uint32_t As[128][33];
    __shared__ uint32_t Bs[32][65];
    const int tid = threadIdx.x;
    const int lane = tid & 31;
    const int warp = tid >> 5;
    const int wm = warp >> 1, wn = warp & 1;

    float acc[2][4][4];
    #pragma unroll
    for (int s = 0; s < 2; s++)
        #pragma unroll
        for (int u = 0; u < 4; u++)
            #pragma unroll
            for (int i = 0; i < 4; i++) acc[s][u][i] = 0.f;

    for (int k0 = 0; k0 < 512; k0 += 32) {
        {
            int r = tid >> 1;
            int c = (tid & 1) * 16;
            const float* srcA = X + (size_t)(m0 + r) * 512 + k0 + c;
            #pragma unroll
            for (int i = 0; i < 4; i++) {
                float4 v = *(const float4*)(srcA + 4 * i);
                As[r][c + 4*i + 0] = f2tf32(v.x);
                As[r][c + 4*i + 1] = f2tf32(v.y);
                As[r][c + 4*i + 2] = f2tf32(v.z);
                As[r][c + 4*i + 3] = f2tf32(v.w);
            }
        }
        {
            int r = tid >> 3;
            int c = (tid & 7) * 8;
            const float* srcB = g_Wxp + (size_t)(k0 + r) * 2048 + n0 + c;
            #pragma unroll
            for (int i = 0; i < 2; i++) {
                float4 v = *(const float4*)(srcB + 4 * i);
                Bs[r][c + 4*i + 0] = f2tf32(v.x);
                Bs[r][c + 4*i + 1] = f2tf32(v.y);
                Bs[r][c + 4*i + 2] = f2tf32(v.z);
                Bs[r][c + 4*i + 3] = f2tf32(v.w);
            }
        }
        __syncthreads();

        #pragma unroll
        for (int ks = 0; ks < 4; ks++) {
            uint32_t a[2][4], bb[4][2];
            const int kk = ks * 8 + (lane & 3);
            #pragma unroll
            for (int s = 0; s < 2; s++) {
                int rr = wm * 32 + s * 16 + (lane >> 2);
                a[s][0] = As[rr][kk];
                a[s][1] = As[rr + 8][kk];
                a[s][2] = As[rr][kk + 4];
                a[s][3] = As[rr + 8][kk + 4];
            }
            #pragma unroll
            for (int u = 0; u < 4; u++) {
                int cc = wn * 32 + u * 8 + (lane >> 2);
                bb[u][0] = Bs[kk][cc];
                bb[u][1] = Bs[kk + 4][cc];
            }
            #pragma unroll
            for (int s = 0; s < 2; s++)
                #pragma unroll
                for (int u = 0; u < 4; u++)
                    mma8(acc[s][u], a[s], bb[u]);
        }
        __syncthreads();
    }

    #pragma unroll
    for (int s = 0; s < 2; s++) {
        int row = m0 + wm * 32 + s * 16 + (lane >> 2);
        #pragma unroll
        for (int u = 0; u < 4; u++) {
            int col = n0 + wn * 32 + u * 8 + 2 * (lane & 3);
            float b0 = g_bp[col], b1 = g_bp[col + 1];
            size_t base = (size_t)row * 2048 + col;
            *(__half2*)(g_preh + base) =
                __floats2half2_rn(acc[s][u][0] + b0, acc[s][u][1] + b1);
            *(__half2*)(g_preh + base + (size_t)8 * 2048) =
                __floats2half2_rn(acc[s][u][2] + b0, acc[s][u][3] + b1);
        }
    }
}

// ---------------------------------------------------------------------------
// Kernel 2a: sort batch rows by num_words descending (stable).
// ---------------------------------------------------------------------------
__global__ void sort_kernel(const int* __restrict__ nw) {
    int b = threadIdx.x;
    if (b < BB) {
        int my = nw[b];
        int rank = 0;
        for (int j = 0; j < BB; j++) {
            int v = nw[j];
            rank += (v > my) || (v == my && j < b);
        }
        g_srcb[rank] = b;
        g_nws[rank] = my;
    }
}

// ---------------------------------------------------------------------------
// Kernel 2b: init — reset counters, publish fp16 initial h (sorted order).
// ---------------------------------------------------------------------------
__global__ void init_state_kernel(const float* __restrict__ ih) {
    int i = blockIdx.x * 256 + threadIdx.x;
    if (i < 4) g_qcnt[i] = 0u;
    if (i < BB * HH) {
        int srow = i >> 9;
        int col = i & 511;
        int borig = g_srcb[srow];
        g_hh[0][i] = __float2half_rn(ih[borig * HH + col]);
    }
}

// ---------------------------------------------------------------------------
// Kernel 3: persistent LSTM recurrence, fp16 HMMA (m16n8k16, fp32 accum).
// 128 CTAs = 4 sorted batch quarters x 32 col' chunks of 64.
// NEW: Wh MMA fragments live permanently in REGISTERS (static operand) —
// per-step LDS traffic is A-side only. h refill via cp.async (L1-bypass).
// ---------------------------------------------------------------------------
__global__ void __launch_bounds__(256, 1) lstm_persist_kernel(
    const float* __restrict__ ic, const float* __restrict__ ih,
    float* __restrict__ out, float* __restrict__ c_final, float* __restrict__ h_final)
{
    extern __shared__ unsigned char smraw[];
    uint32_t* As32 = (uint32_t*)smraw;                                   // [32][AS2] b32 (fp16x2)
    uint32_t* Bt32 = (uint32_t*)(smraw + ROWS * AS2 * 4);                // [64][BS2] b32 (B^T)
    float*    zs   = (float*)(smraw + ROWS * AS2 * 4 + NC * BS2 * 4);    // [4][32][ZST]

    uint32_t as_base;
    asm("{ .reg .u64 t; cvta.to.shared.u64 t, %1; cvt.u32.u64 %0, t; }"
        : "=r"(as_base) : "l"(As32));

    const int tid  = threadIdx.x;
    const int lane = tid & 31;
    const int warp = tid >> 5;
    const int rb = blockIdx.x & 3;        // batch quarter (sorted order)
    const int cn = blockIdx.x >> 2;       // 0..31 col' chunk
    const int n0 = cn * NC;               // col' base

    // --- one-time: load Wh^T slice into SMEM (fp16 pairs along k) ---
    {
        int cc  = tid >> 2;               // 0..63
        int seg = tid & 3;                // quarter of the 512-k row
        const uint4* src = (const uint4*)(g_WhT + (size_t)(n0 + cc) * 512 + seg * 128);
        uint32_t* dst = Bt32 + cc * BS2 + seg * 64;
        #pragma unroll
        for (int i = 0; i < 16; i++) {
            uint4 v = src[i];
            *(uint4*)(dst + i * 4) = v;
        }
    }

    // --- epilogue mapping: thread owns (srow, hc0) and (srow, hc0+1) ---
    const int r_ep = tid & 31;                 // local batch row
    const int hl2  = (tid >> 5) * 2;           // local h col pair (0,2,..,14)
    const int srow = rb * ROWS + r_ep;         // sorted batch row
    const int borig = g_srcb[srow];            // original batch row
    const int mynw  = g_nws[srow];
    const int qmax  = g_nws[rb * ROWS];        // max num_words in this quarter
    float c0  = ic[borig * HH + cn * 16 + hl2];
    float c1  = ic[borig * HH + cn * 16 + hl2 + 1];
    float hr0 = ih[borig * HH + cn * 16 + hl2];
    float hr1 = ih[borig * HH + cn * 16 + hl2 + 1];
    const size_t outcol = (size_t)borig * HH + cn * 16 + hl2;

    // --- MMA mapping: 8 warps = 2 n-halves x 4 K-slices; warp tile 32x32 ---
    const int wn = warp & 1;
    const int kw = warp >> 1;
    const int kwb = kw * 64;                   // K-slice base in b32 units
    const int ln4 = lane >> 2;
    const int kl  = lane & 3;

    // --- A-fill mapping: 32 rows x 64 uint4 (8 halves each) ---
    const int fr = tid >> 3;                   // row 0..31
    const int fc = tid & 7;                    // uint4 group

    unsigned* const qcnt = &g_qcnt[rb];

    __syncthreads();                           // Bt ready

    // --- load Wh fragments into registers ONCE (static across all steps) ---
    uint32_t breg[8][4][2];
    #pragma unroll
    for (int ks = 0; ks < 8; ks++) {
        const int kb = kwb + ks * 8 + kl;
        #pragma unroll
        for (int u = 0; u < 4; u++) {
            int cc = wn * 32 + u * 8 + ln4;
            breg[ks][u][0] = Bt32[cc * BS2 + kb];
            breg[ks][u][1] = Bt32[cc * BS2 + kb + 4];
        }
    }

    // prefetch pre-activations for step 0 (8 fp16 gate values)
    uint4 praw = make_uint4(0, 0, 0, 0);
    if (qmax > 0)
        praw = __ldcs((const uint4*)(g_preh + ((size_t)borig * TT) * 2048 + n0 + hl2 * 4));

    for (int t = 0; t < qmax; t++) {
        const __half* __restrict__ h_in  = g_hh[t & 1];
        __half*       __restrict__ h_out = g_hh[(t & 1) ^ 1];

        // fill As with this quarter's 32 h rows via cp.async (L1-bypass .cg)
        {
            const __half* src = h_in + (size_t)(rb * ROWS + fr) * HH + fc * 8;
            uint32_t dstb = as_base + (uint32_t)(fr * AS2 + fc * 4) * 4u;
            #pragma unroll
            for (int j = 0; j < 8; j++) {
                asm volatile("cp.async.cg.shared.global [%0], [%1], 16;"
                             :: "r"(dstb + (uint32_t)(j * 32 * 4)),
                                "l"(src + j * 64) : "memory");
            }
            asm volatile("cp.async.commit_group;" ::: "memory");
            asm volatile("cp.async.wait_group 0;" ::: "memory");
        }
        __syncthreads();

        // GEMM: [32 x 128] @ [128 x 32] per warp (K-slice kw, n-half wn)
        // B fragments already in registers; only A-side LDS per step.
        float acc[2][4][4];
        #pragma unroll
        for (int s = 0; s < 2; s++)
            #pragma unroll
            for (int u = 0; u < 4; u++)
                #pragma unroll
                for (int i = 0; i < 4; i++) acc[s][u][i] = 0.f;

        #pragma unroll
        for (int ks = 0; ks < 8; ks++) {
            const int kb = kwb + ks * 8 + kl;
            uint32_t a[2][4];
            #pragma unroll
            for (int s = 0; s < 2; s++) {
                int rr = s * 16 + ln4;
                a[s][0] = As32[rr * AS2 + kb];
                a[s][1] = As32[(rr + 8) * AS2 + kb];
                a[s][2] = As32[rr * AS2 + kb + 4];
                a[s][3] = As32[(rr + 8) * AS2 + kb + 4];
            }
            #pragma unroll
            for (int s = 0; s < 2; s++)
                #pragma unroll
                for (int u = 0; u < 4; u++)
                    mma16h(acc[s][u], a[s], breg[ks][u]);
        }

        // store partials: zs[kw][row][col] (separate region — no sync needed)
        {
            int zcb = wn * 32 + 2 * kl;
            #pragma unroll
            for (int s = 0; s < 2; s++) {
                int row = s * 16 + ln4;
                #pragma unroll
                for (int u = 0; u < 4; u++) {
                    int col = zcb + u * 8;
                    *(float2*)&zs[(kw * 32 + row) * ZST + col]     =
                        make_float2(acc[s][u][0], acc[s][u][1]);
                    *(float2*)&zs[(kw * 32 + row + 8) * ZST + col] =
                        make_float2(acc[s][u][2], acc[s][u][3]);
                }
            }
        }
        __syncthreads();

        // reduce 4 K-partials + fused gate epilogue (2 owned h cols)
        float4 z0 = make_float4(0.f, 0.f, 0.f, 0.f);
        float4 z1 = make_float4(0.f, 0.f, 0.f, 0.f);
        #pragma unroll
        for (int s = 0; s < 4; s++) {
            const float* zp = zs + ((s * 32 + r_ep) * ZST + hl2 * 4);
            float4 a0 = *(const float4*)zp;
            float4 a1 = *(const float4*)(zp + 4);
            z0.x += a0.x; z0.y += a0.y; z0.z += a0.z; z0.w += a0.w;
            z1.x += a1.x; z1.y += a1.y; z1.z += a1.z; z1.w += a1.w;
        }

        // unpack prefetched fp16 pre-activations
        const __half2* ph = (const __half2*)&praw;
        float2 q0 = __half22float2(ph[0]);   // (i,j) of hc0
        float2 q1 = __half22float2(ph[1]);   // (f,o) of hc0
        float2 q2 = __half22float2(ph[2]);   // (i,j) of hc0+1
        float2 q3 = __half22float2(ph[3]);   // (f,o) of hc0+1

        float zi0 = z0.x + q0.x, zj0 = z0.y + q0.y, zf0 = z0.z + q1.x, zo0 = z0.w + q1.y;
        float zi1 = z1.x + q2.x, zj1 = z1.y + q2.y, zf1 = z1.z + q3.x, zo1 = z1.w + q3.y;

        float si0 = 1.f / (1.f + __expf(-zi0));
        float sf0 = 1.f / (1.f + __expf(-(zf0 + 1.0f)));
        float so0 = 1.f / (1.f + __expf(-zo0));
        float tj0 = tanhf(zj0);
        float nc0 = c0 * sf0 + si0 * tj0;
        float nh0 = tanhf(nc0) * so0;

        float si1 = 1.f / (1.f + __expf(-zi1));
        float sf1 = 1.f / (1.f + __expf(-(zf1 + 1.0f)));
        float so1 = 1.f / (1.f + __expf(-zo1));
        float tj1 = tanhf(zj1);
        float nc1 = c1 * sf1 + si1 * tj1;
        float nh1 = tanhf(nc1) * so1;

        bool m = t < mynw;
        c0 = m ? nc0 : c0;   c1 = m ? nc1 : c1;
        hr0 = m ? nh0 : hr0; hr1 = m ? nh1 : hr1;

        size_t sidx = (size_t)srow * HH + cn * 16 + hl2;
        *(__half2*)(h_out + sidx) = __floats2half2_rn(hr0, hr1);
        __stcs((float2*)&out[(size_t)t * (BB * HH) + outcol],
               make_float2(m ? nh0 : 0.f, m ? nh1 : 0.f));

        // quarter-local barrier — only while a next step will consume h
        if (t + 1 < qmax) {
            praw = __ldcs((const uint4*)(g_preh +
                       ((size_t)borig * TT + (t + 1)) * 2048 + n0 + hl2 * 4));

            __syncthreads();                       // all h_out stores issued CTA-wide
            if (tid == 0) {
                asm volatile("red.release.gpu.add.u32 [%0], %1;"
                             :: "l"(qcnt), "r"(1u) : "memory");
                unsigned target = 32u * (unsigned)(t + 1);
                unsigned v;
                do {
                    asm volatile("ld.acquire.gpu.u32 %0, [%1];"
                                 : "=r"(v) : "l"(qcnt) : "memory");
                } while (v < target);
            }
            __syncthreads();                       // acquire propagates CTA-wide
        }
    }

    // bulk zeros for the inactive tail (off the critical path)
    for (int t = qmax; t < TT; t++)
        __stcs((float2*)&out[(size_t)t * (BB * HH) + outcol], make_float2(0.f, 0.f));

    // final states (each (b,h) pair owned by exactly one thread)
    *(float2*)&c_final[outcol] = make_float2(c0, c1);
    *(float2*)&h_final[outcol] = make_float2(hr0, hr1);
}

// ---------------------------------------------------------------------------
extern "C" void kernel_launch(void* const* d_in, const int* in_sizes, int n_in,
                              void* d_out, int out_size) {
    const float* x    = (const float*)d_in[0];  // [B,T,D]
    const int*   nw   = (const int*)  d_in[1];  // [B]
    const float* ic   = (const float*)d_in[2];  // [B,H]
    const float* ih   = (const float*)d_in[3];  // [B,H]
    const float* W    = (const float*)d_in[4];  // [D+H, 4H]
    const float* bias = (const float*)d_in[5];  // [4H]

    float* out     = (float*)d_out;
    float* c_final = out + (size_t)TT * BB * HH;
    float* h_final = c_final + (size_t)BB * HH;

    const int smem_bytes = ROWS * AS2 * 4 + NC * BS2 * 4 + 4 * ROWS * ZST * 4; // 134656
    cudaFuncSetAttribute(lstm_persist_kernel,
                         cudaFuncAttributeMaxDynamicSharedMemorySize, smem_bytes);

    permute_W_kernel<<<8192, 256>>>(W, bias);
    gemm_x_kernel<<<dim3(32, 512), 256>>>(x, nw);
    sort_kernel<<<1, 128>>>(nw);
    init_state_kernel<<<(BB * HH + 255) / 256, 256>>>(ih);
    lstm_persist_kernel<<<NCTA, 256, smem_bytes>>>(ic, ih, out, c_final, h_final);
}

// round 11
// speedup vs baseline: 2.0437x; 1.3840x over previous
#include <cuda_runtime.h>
#include <cuda_fp16.h>
#include <cstdint>

// Problem constants
#define BB 128
#define TT 512
#define DD 512
#define HH 512
#define G4 2048            // 4*H
#define MX (BB*TT)

// Persistent-kernel tiling
#define NCTA 128
#define ROWS 32            // batch rows per CTA (one quarter)
#define NC   64            // permuted cols per CTA (=> 16 h cols)
#define AS2  260           // As stride in b32 units (256 + 4; 260%32==4 -> conflict-free)
#define BS2  260           // Bt stride in b32 units
#define ZST  68            // zs stride in floats

// gemm_x fp16 tiling
#define XA2 20             // A stride in half2 units (16 + 4 pad)
#define XB2 20             // B stride in half2 units

// Device scratch (allocation-free requirement: __device__ globals)
__device__ __half g_preh[(size_t)MX * G4];   // 256 MB: x@Wx + b (fp16), permuted cols
__device__ __half g_WxT[G4 * DD];            // permuted input weights, TRANSPOSED [col'][k], fp16
__device__ __half g_WhT[G4 * HH];            // permuted recurrent weights, TRANSPOSED [col'][k]
__device__ float  g_bp[G4];                  // permuted bias
__device__ __half g_hh[2][BB * HH];          // ping-pong hidden state (fp16, sorted order)
__device__ int    g_srcb[BB];                // sorted pos -> original batch row
__device__ int    g_nws[BB];                 // num_words, sorted descending
__device__ unsigned g_qcnt[4];               // per-quarter barrier counters

__device__ __forceinline__ uint32_t h2u(__half2 v) {
    return *reinterpret_cast<uint32_t*>(&v);
}

__device__ __forceinline__ void mma16h(float d[4], const uint32_t a[4], const uint32_t b[2]) {
    asm volatile(
        "mma.sync.aligned.m16n8k16.row.col.f32.f16.f16.f32 "
        "{%0,%1,%2,%3}, {%4,%5,%6,%7}, {%8,%9}, {%0,%1,%2,%3};"
        : "+f"(d[0]), "+f"(d[1]), "+f"(d[2]), "+f"(d[3])
        : "r"(a[0]), "r"(a[1]), "r"(a[2]), "r"(a[3]), "r"(b[0]), "r"(b[1]));
}

// ---------------------------------------------------------------------------
// Kernel 0: permute W (col' = 4*h + g) into fp16 transposed layouts, permute
// bias, AND (extra block 8192) sort batch rows by num_words descending.
// ---------------------------------------------------------------------------
__global__ void permute_W_kernel(const float* __restrict__ W, const float* __restrict__ bias,
                                 const int* __restrict__ nw) {
    if (blockIdx.x == 8192) {       // fused sort block
        int b = threadIdx.x;
        if (b < BB) {
            int my = nw[b];
            int rank = 0;
            for (int j = 0; j < BB; j++) {
                int v = nw[j];
                rank += (v > my) || (v == my && j < b);
            }
            g_srcb[rank] = b;
            g_nws[rank] = my;
        }
        return;
    }
    int idx = blockIdx.x * 256 + threadIdx.x;
    if (idx < 1024 * 2048) {
        int d = idx >> 11;
        int col = idx & 2047;
        int g = col >> 9;
        int h = col & 511;
        int colp = 4 * h + g;
        __half v = __float2half_rn(W[idx]);
        if (d < 512) g_WxT[(size_t)colp * 512 + d]         = v;
        else         g_WhT[(size_t)colp * 512 + (d - 512)] = v;
    }
    if (idx < 2048) {
        int g = idx >> 9;
        int h = idx & 511;
        g_bp[4 * h + g] = bias[idx];
    }
}

// ---------------------------------------------------------------------------
// Kernel 1: input projection GEMM  g_preh = fp16(X @ Wx + b), fp16 HMMA.
// A = X block (128 m x 32 k, cvt fp32->fp16 on stage), B = WxT rows [n][k].
// Skips blocks whose 128 timesteps are all masked.
// ---------------------------------------------------------------------------
__global__ void __launch_bounds__(256) gemm_x_kernel(const float* __restrict__ X,
                                                     const int* __restrict__ nw) {
    const int n0 = blockIdx.x * 64;
    const int m0 = blockIdx.y * 128;
    {
        int b = m0 >> 9;
        int t0 = m0 & 511;
        if (t0 >= nw[b]) return;
    }
    __shared__ uint32_t As[128 * XA2];   // [row][k-half2]
    __shared__ uint32_t Bs[64 * XB2];    // [n][k-half2]  (B^T: col-major for MMA)
    const int tid = threadIdx.x;
    const int lane = tid & 31;
    const int warp = tid >> 5;
    const int wm = warp >> 1, wn = warp & 1;
    const int ln4 = lane >> 2;
    const int kl  = lane & 3;

    float acc[2][4][4];
    #pragma unroll
    for (int s = 0; s < 2; s++)
        #pragma unroll
        for (int u = 0; u < 4; u++)
            #pragma unroll
            for (int i = 0; i < 4; i++) acc[s][u][i] = 0.f;

    for (int k0 = 0; k0 < 512; k0 += 32) {
        // A stage: 128 rows x 32 k fp16. 2 threads/row, 16 floats each.
        {
            int r = tid >> 1;
            int cg = (tid & 1) * 8;                 // half2 group base
            const float* srcA = X + (size_t)(m0 + r) * 512 + k0 + (tid & 1) * 16;
            #pragma unroll
            for (int i = 0; i < 4; i++) {
                float4 v = *(const float4*)(srcA + 4 * i);
                As[r * XA2 + cg + 2 * i]     = h2u(__floats2half2_rn(v.x, v.y));
                As[r * XA2 + cg + 2 * i + 1] = h2u(__floats2half2_rn(v.z, v.w));
            }
        }
        // B stage: 64 n-rows x 32 k fp16, straight copy from WxT rows.
        {
            int n = tid >> 2;
            int seg = tid & 3;                      // 8 halves = 1 uint4
            uint4 v = *(const uint4*)(g_WxT + (size_t)(n0 + n) * 512 + k0 + seg * 8);
            Bs[n * XB2 + seg * 4 + 0] = v.x;
            Bs[n * XB2 + seg * 4 + 1] = v.y;
            Bs[n * XB2 + seg * 4 + 2] = v.z;
            Bs[n * XB2 + seg * 4 + 3] = v.w;
        }
        __syncthreads();

        #pragma unroll
        for (int ks = 0; ks < 2; ks++) {
            const int kb = ks * 8 + kl;
            uint32_t a[2][4], bb[4][2];
            #pragma unroll
            for (int s = 0; s < 2; s++) {
                int rr = wm * 32 + s * 16 + ln4;
                a[s][0] = As[rr * XA2 + kb];
                a[s][1] = As[(rr + 8) * XA2 + kb];
                a[s][2] = As[rr * XA2 + kb + 4];
                a[s][3] = As[(rr + 8) * XA2 + kb + 4];
            }
            #pragma unroll
            for (int u = 0; u < 4; u++) {
                int cc = wn * 32 + u * 8 + ln4;
                bb[u][0] = Bs[cc * XB2 + kb];
                bb[u][1] = Bs[cc * XB2 + kb + 4];
            }
            #pragma unroll
            for (int s = 0; s < 2; s++)
                #pragma unroll
                for (int u = 0; u < 4; u++)
                    mma16h(acc[s][u], a[s], bb[u]);
        }
        __syncthreads();
    }

    #pragma unroll
    for (int s = 0; s < 2; s++) {
        int row = m0 + wm * 32 + s * 16 + (lane >> 2);
        #pragma unroll
        for (int u = 0; u < 4; u++) {
            int col = n0 + wn * 32 + u * 8 + 2 * (lane & 3);
            float b0 = g_bp[col], b1 = g_bp[col + 1];
            size_t base = (size_t)row * 2048 + col;
            *(__half2*)(g_preh + base) =
                __floats2half2_rn(acc[s][u][0] + b0, acc[s][u][1] + b1);
            *(__half2*)(g_preh + base + (size_t)8 * 2048) =
                __floats2half2_rn(acc[s][u][2] + b0, acc[s][u][3] + b1);
        }
    }
}

// ---------------------------------------------------------------------------
// Kernel 2: init — reset counters, publish fp16 initial h (sorted order).
// ---------------------------------------------------------------------------
__global__ void init_state_kernel(const float* __restrict__ ih) {
    int i = blockIdx.x * 256 + threadIdx.x;
    if (i < 4) g_qcnt[i] = 0u;
    if (i < BB * HH) {
        int srow = i >> 9;
        int col = i & 511;
        int borig = g_srcb[srow];
        g_hh[0][i] = __float2half_rn(ih[borig * HH + col]);
    }
}

// ---------------------------------------------------------------------------
// Kernel 3: persistent LSTM recurrence, fp16 HMMA (m16n8k16, fp32 accum).
// 128 CTAs = 4 sorted batch quarters x 32 col' chunks of 64.
// Wh MMA fragments permanently in registers; h refill via cp.async.
// ---------------------------------------------------------------------------
__global__ void __launch_bounds__(256, 1) lstm_persist_kernel(
    const float* __restrict__ ic, const float* __restrict__ ih,
    float* __restrict__ out, float* __restrict__ c_final, float* __restrict__ h_final)
{
    extern __shared__ unsigned char smraw[];
    uint32_t* As32 = (uint32_t*)smraw;                                   // [32][AS2] b32 (fp16x2)
    uint32_t* Bt32 = (uint32_t*)(smraw + ROWS * AS2 * 4);                // [64][BS2] b32 (B^T)
    float*    zs   = (float*)(smraw + ROWS * AS2 * 4 + NC * BS2 * 4);    // [4][32][ZST]

    uint32_t as_base;
    asm("{ .reg .u64 t; cvta.to.shared.u64 t, %1; cvt.u32.u64 %0, t; }"
        : "=r"(as_base) : "l"(As32));

    const int tid  = threadIdx.x;
    const int lane = tid & 31;
    const int warp = tid >> 5;
    const int rb = blockIdx.x & 3;        // batch quarter (sorted order)
    const int cn = blockIdx.x >> 2;       // 0..31 col' chunk
    const int n0 = cn * NC;               // col' base

    // --- one-time: load Wh^T slice into SMEM (fp16 pairs along k) ---
    {
        int cc  = tid >> 2;               // 0..63
        int seg = tid & 3;                // quarter of the 512-k row
        const uint4* src = (const uint4*)(g_WhT + (size_t)(n0 + cc) * 512 + seg * 128);
        uint32_t* dst = Bt32 + cc * BS2 + seg * 64;
        #pragma unroll
        for (int i = 0; i < 16; i++) {
            uint4 v = src[i];
            *(uint4*)(dst + i * 4) = v;
        }
    }

    // --- epilogue mapping: thread owns (srow, hc0) and (srow, hc0+1) ---
    const int r_ep = tid & 31;                 // local batch row
    const int hl2  = (tid >> 5) * 2;           // local h col pair (0,2,..,14)
    const int srow = rb * ROWS + r_ep;         // sorted batch row
    const int borig = g_srcb[srow];            // original batch row
    const int mynw  = g_nws[srow];
    const int qmax  = g_nws[rb * ROWS];        // max num_words in this quarter
    float c0  = ic[borig * HH + cn * 16 + hl2];
    float c1  = ic[borig * HH + cn * 16 + hl2 + 1];
    float hr0 = ih[borig * HH + cn * 16 + hl2];
    float hr1 = ih[borig * HH + cn * 16 + hl2 + 1];
    const size_t outcol = (size_t)borig * HH + cn * 16 + hl2;

    // --- MMA mapping: 8 warps = 2 n-halves x 4 K-slices; warp tile 32x32 ---
    const int wn = warp & 1;
    const int kw = warp >> 1;
    const int kwb = kw * 64;                   // K-slice base in b32 units
    const int ln4 = lane >> 2;
    const int kl  = lane & 3;

    // --- A-fill mapping: 32 rows x 64 uint4 (8 halves each) ---
    const int fr = tid >> 3;                   // row 0..31
    const int fc = tid & 7;                    // uint4 group

    unsigned* const qcnt = &g_qcnt[rb];

    __syncthreads();                           // Bt ready

    // --- load Wh fragments into registers ONCE (static across all steps) ---
    uint32_t breg[8][4][2];
    #pragma unroll
    for (int ks = 0; ks < 8; ks++) {
        const int kb = kwb + ks * 8 + kl;
        #pragma unroll
        for (int u = 0; u < 4; u++) {
            int cc = wn * 32 + u * 8 + ln4;
            breg[ks][u][0] = Bt32[cc * BS2 + kb];
            breg[ks][u][1] = Bt32[cc * BS2 + kb + 4];
        }
    }

    // prefetch pre-activations for step 0 (8 fp16 gate values)
    uint4 praw = make_uint4(0, 0, 0, 0);
    if (qmax > 0)
        praw = __ldcs((const uint4*)(g_preh + ((size_t)borig * TT) * 2048 + n0 + hl2 * 4));

    for (int t = 0; t < qmax; t++) {
        const __half* __restrict__ h_in  = g_hh[t & 1];
        __half*       __restrict__ h_out = g_hh[(t & 1) ^ 1];

        // fill As with this quarter's 32 h rows via cp.async (L1-bypass .cg)
        {
            const __half* src = h_in + (size_t)(rb * ROWS + fr) * HH + fc * 8;
            uint32_t dstb = as_base + (uint32_t)(fr * AS2 + fc * 4) * 4u;
            #pragma unroll
            for (int j = 0; j < 8; j++) {
                asm volatile("cp.async.cg.shared.global [%0], [%1], 16;"
                             :: "r"(dstb + (uint32_t)(j * 32 * 4)),
                                "l"(src + j * 64) : "memory");
            }
            asm volatile("cp.async.commit_group;" ::: "memory");
            asm volatile("cp.async.wait_group 0;" ::: "memory");
        }
        __syncthreads();

        // GEMM: [32 x 128] @ [128 x 32] per warp (K-slice kw, n-half wn)
        float acc[2][4][4];
        #pragma unroll
        for (int s = 0; s < 2; s++)
            #pragma unroll
            for (int u = 0; u < 4; u++)
                #pragma unroll
                for (int i = 0; i < 4; i++) acc[s][u][i] = 0.f;

        #pragma unroll
        for (int ks = 0; ks < 8; ks++) {
            const int kb = kwb + ks * 8 + kl;
            uint32_t a[2][4];
            #pragma unroll
            for (int s = 0; s < 2; s++) {
                int rr = s * 16 + ln4;
                a[s][0] = As32[rr * AS2 + kb];
                a[s][1] = As32[(rr + 8) * AS2 + kb];
                a[s][2] = As32[rr * AS2 + kb + 4];
                a[s][3] = As32[(rr + 8) * AS2 + kb + 4];
            }
            #pragma unroll
            for (int s = 0; s < 2; s++)
                #pragma unroll
                for (int u = 0; u < 4; u++)
                    mma16h(acc[s][u], a[s], breg[ks][u]);
        }

        // store partials: zs[kw][row][col]
        {
            int zcb = wn * 32 + 2 * kl;
            #pragma unroll
            for (int s = 0; s < 2; s++) {
                int row = s * 16 + ln4;
                #pragma unroll
                for (int u = 0; u < 4; u++) {
                    int col = zcb + u * 8;
                    *(float2*)&zs[(kw * 32 + row) * ZST + col]     =
                        make_float2(acc[s][u][0], acc[s][u][1]);
                    *(float2*)&zs[(kw * 32 + row + 8) * ZST + col] =
                        make_float2(acc[s][u][2], acc[s][u][3]);
                }
            }
        }
        __syncthreads();

        // reduce 4 K-partials + fused gate epilogue (2 owned h cols)
        float4 z0 = make_float4(0.f, 0.f, 0.f, 0.f);
        float4 z1 = make_float4(0.f, 0.f, 0.f, 0.f);
        #pragma unroll
        for (int s = 0; s < 4; s++) {
            const float* zp = zs + ((s * 32 + r_ep) * ZST + hl2 * 4);
            float4 a0 = *(const float4*)zp;
            float4 a1 = *(const float4*)(zp + 4);
            z0.x += a0.x; z0.y += a0.y; z0.z += a0.z; z0.w += a0.w;
            z1.x += a1.x; z1.y += a1.y; z1.z += a1.z; z1.w += a1.w;
        }

        const __half2* ph = (const __half2*)&praw;
        float2 q0 = __half22float2(ph[0]);
        float2 q1 = __half22float2(ph[1]);
        float2 q2 = __half22float2(ph[2]);
        float2 q3 = __half22float2(ph[3]);

        float zi0 = z0.x + q0.x, zj0 = z0.y + q0.y, zf0 = z0.z + q1.x, zo0 = z0.w + q1.y;
        float zi1 = z1.x + q2.x, zj1 = z1.y + q2.y, zf1 = z1.z + q3.x, zo1 = z1.w + q3.y;

        float si0 = 1.f / (1.f + __expf(-zi0));
        float sf0 = 1.f / (1.f + __expf(-(zf0 + 1.0f)));
        float so0 = 1.f / (1.f + __expf(-zo0));
        float tj0 = tanhf(zj0);
        float nc0 = c0 * sf0 + si0 * tj0;
        float nh0 = tanhf(nc0) * so0;

        float si1 = 1.f / (1.f + __expf(-zi1));
        float sf1 = 1.f / (1.f + __expf(-(zf1 + 1.0f)));
        float so1 = 1.f / (1.f + __expf(-zo1));
        float tj1 = tanhf(zj1);
        float nc1 = c1 * sf1 + si1 * tj1;
        float nh1 = tanhf(nc1) * so1;

        bool m = t < mynw;
        c0 = m ? nc0 : c0;   c1 = m ? nc1 : c1;
        hr0 = m ? nh0 : hr0; hr1 = m ? nh1 : hr1;

        size_t sidx = (size_t)srow * HH + cn * 16 + hl2;
        *(__half2*)(h_out + sidx) = __floats2half2_rn(hr0, hr1);
        __stcs((float2*)&out[(size_t)t * (BB * HH) + outcol],
               make_float2(m ? nh0 : 0.f, m ? nh1 : 0.f));

        // quarter-local barrier — only while a next step will consume h
        if (t + 1 < qmax) {
            praw = __ldcs((const uint4*)(g_preh +
                       ((size_t)borig * TT + (t + 1)) * 2048 + n0 + hl2 * 4));

            __syncthreads();                       // all h_out stores issued CTA-wide
            if (tid == 0) {
                asm volatile("red.release.gpu.add.u32 [%0], %1;"
                             :: "l"(qcnt), "r"(1u) : "memory");
                unsigned target = 32u * (unsigned)(t + 1);
                unsigned v;
                do {
                    asm volatile("ld.acquire.gpu.u32 %0, [%1];"
                                 : "=r"(v) : "l"(qcnt) : "memory");
                } while (v < target);
            }
            __syncthreads();                       // acquire propagates CTA-wide
        }
    }

    // bulk zeros for the inactive tail (off the critical path)
    for (int t = qmax; t < TT; t++)
        __stcs((float2*)&out[(size_t)t * (BB * HH) + outcol], make_float2(0.f, 0.f));

    // final states (each (b,h) pair owned by exactly one thread)
    *(float2*)&c_final[outcol] = make_float2(c0, c1);
    *(float2*)&h_final[outcol] = make_float2(hr0, hr1);
}

// ---------------------------------------------------------------------------
extern "C" void kernel_launch(void* const* d_in, const int* in_sizes, int n_in,
                              void* d_out, int out_size) {
    const float* x    = (const float*)d_in[0];  // [B,T,D]
    const int*   nw   = (const int*)  d_in[1];  // [B]
    const float* ic   = (const float*)d_in[2];  // [B,H]
    const float* ih   = (const float*)d_in[3];  // [B,H]
    const float* W    = (const float*)d_in[4];  // [D+H, 4H]
    const float* bias = (const float*)d_in[5];  // [4H]

    float* out     = (float*)d_out;
    float* c_final = out + (size_t)TT * BB * HH;
    float* h_final = c_final + (size_t)BB * HH;

    const int smem_bytes = ROWS * AS2 * 4 + NC * BS2 * 4 + 4 * ROWS * ZST * 4; // 134656
    cudaFuncSetAttribute(lstm_persist_kernel,
                         cudaFuncAttributeMaxDynamicSharedMemorySize, smem_bytes);

    permute_W_kernel<<<8193, 256>>>(W, bias, nw);       // includes fused sort block
    gemm_x_kernel<<<dim3(32, 512), 256>>>(x, nw);
    init_state_kernel<<<(BB * HH + 255) / 256, 256>>>(ih);
    lstm_persist_kernel<<<NCTA, 256, smem_bytes>>>(ic, ih, out, c_final, h_final);
}